// round 1
// baseline (speedup 1.0000x reference)
#include <cuda_runtime.h>
#include <cstdint>

// ---------------------------------------------------------------------------
// BeatDetectionRSNN2: 2-layer IF-neuron SNN.
//   K1: Y[b,t,d] = sum_k x[b,t,k] * W1[d,k]          (big fp32 GEMM, parallel)
//   K2: serial scan over t per batch b:
//         v1 += y_t; s1 = (v1>=1); v1 *= (1-s1)
//         v2 += s1 @ W2^T; s2 = (v2>=1); v2 *= (1-s2); out = s2
// ---------------------------------------------------------------------------

#define B_  128
#define T_  4096
#define D_  128
#define O_  2

// 256 MB scratch for Y (device global => no allocation in kernel_launch)
__device__ float g_Y[(size_t)B_ * T_ * D_];

// packed fp32x2 FMA (sm_100a) — ptxas will not auto-generate FFMA2
union F2U { float2 f; unsigned long long u; };
__device__ __forceinline__ float2 fma2(float2 a, float2 b, float2 c) {
    F2U A, Bv, C, Dv; A.f = a; Bv.f = b; C.f = c;
    asm("fma.rn.f32x2 %0, %1, %2, %3;" : "=l"(Dv.u) : "l"(A.u), "l"(Bv.u), "l"(C.u));
    return Dv.f;
}

// ---------------------------------------------------------------------------
// K1: tiled fp32 GEMM, C[M=524288,128] = X[M,128] * W1^T  (W1 is [128,128] row-major [d][k])
// Block tile 128x128, K-chunk 32, 256 threads, 8x8 micro-tile via FFMA2.
// ---------------------------------------------------------------------------
#define BK 32
#define LDP 132   // padded row pitch (floats) for k-major smem tiles

__global__ __launch_bounds__(256, 2)
void gemm_xw1(const float* __restrict__ X, const float* __restrict__ W1)
{
    __shared__ float As[BK * LDP];   // As[k][m], m contiguous
    __shared__ float Bs[BK * LDP];   // Bs[k][n], n contiguous (= W1[n][k])

    const int tid = threadIdx.x;
    const int tx  = tid & 15;        // n-tile index  (n0 = tx*8)
    const int ty  = tid >> 4;        // m-tile index  (m0 = ty*8)
    const int m0  = blockIdx.x * 128;

    const int rl = tid >> 3;         // 0..31 row within load pass
    const int c4 = (tid & 7) * 4;    // 0,4,...,28 col within K-chunk

    float2 acc[8][4];
#pragma unroll
    for (int i = 0; i < 8; i++)
#pragma unroll
        for (int j = 0; j < 4; j++) acc[i][j] = make_float2(0.f, 0.f);

    for (int kc = 0; kc < 128; kc += BK) {
        // load X tile (128 rows x 32 k) transposed into As[k][m]
#pragma unroll
        for (int rr = 0; rr < 128; rr += 32) {
            float4 v = *(const float4*)&X[(size_t)(m0 + rr + rl) * 128 + kc + c4];
            As[(c4 + 0) * LDP + rr + rl] = v.x;
            As[(c4 + 1) * LDP + rr + rl] = v.y;
            As[(c4 + 2) * LDP + rr + rl] = v.z;
            As[(c4 + 3) * LDP + rr + rl] = v.w;
        }
        // load W1 tile (128 n x 32 k) transposed into Bs[k][n]
#pragma unroll
        for (int nn = 0; nn < 128; nn += 32) {
            float4 v = *(const float4*)&W1[(size_t)(nn + rl) * 128 + kc + c4];
            Bs[(c4 + 0) * LDP + nn + rl] = v.x;
            Bs[(c4 + 1) * LDP + nn + rl] = v.y;
            Bs[(c4 + 2) * LDP + nn + rl] = v.z;
            Bs[(c4 + 3) * LDP + nn + rl] = v.w;
        }
        __syncthreads();

#pragma unroll
        for (int k = 0; k < BK; k++) {
            const float* ap = &As[k * LDP + ty * 8];
            const float* bp = &Bs[k * LDP + tx * 8];
            float4 a0 = *(const float4*)(ap);
            float4 a1 = *(const float4*)(ap + 4);
            float4 b0 = *(const float4*)(bp);
            float4 b1 = *(const float4*)(bp + 4);
            float  av[8] = {a0.x, a0.y, a0.z, a0.w, a1.x, a1.y, a1.z, a1.w};
            float2 bv[4] = {{b0.x, b0.y}, {b0.z, b0.w}, {b1.x, b1.y}, {b1.z, b1.w}};
#pragma unroll
            for (int i = 0; i < 8; i++) {
                float2 ad = make_float2(av[i], av[i]);
#pragma unroll
                for (int j = 0; j < 4; j++)
                    acc[i][j] = fma2(ad, bv[j], acc[i][j]);
            }
        }
        __syncthreads();
    }

    const int row0 = m0 + ty * 8;
    const int col0 = tx * 8;
#pragma unroll
    for (int i = 0; i < 8; i++) {
        float4 o0 = make_float4(acc[i][0].x, acc[i][0].y, acc[i][1].x, acc[i][1].y);
        float4 o1 = make_float4(acc[i][2].x, acc[i][2].y, acc[i][3].x, acc[i][3].y);
        *(float4*)&g_Y[(size_t)(row0 + i) * 128 + col0]     = o0;
        *(float4*)&g_Y[(size_t)(row0 + i) * 128 + col0 + 4] = o1;
    }
}

// ---------------------------------------------------------------------------
// K2: serial scan. One warp per batch element. Lane l owns d = 4l..4l+3.
// The 32->1 butterfly reduction for layer 2 is software-pipelined: one of the
// five shfl levels per loop iteration (result applied with a 5-step delay), so
// the ~150-cycle shfl dependency chain never blocks a single iteration.
// ---------------------------------------------------------------------------
__global__ void snn_scan(const float* __restrict__ W2, float* __restrict__ out)
{
    const int b    = blockIdx.x;
    const int lane = threadIdx.x;           // 0..31
    const unsigned FULL = 0xffffffffu;

    const float* yb = g_Y + (size_t)b * T_ * D_ + lane * 4;
    float* ob = out + (size_t)b * T_ * O_;

    float w20[4], w21[4];
    {
        float4 t0 = *(const float4*)(W2 + lane * 4);
        float4 t1 = *(const float4*)(W2 + 128 + lane * 4);
        w20[0] = t0.x; w20[1] = t0.y; w20[2] = t0.z; w20[3] = t0.w;
        w21[0] = t1.x; w21[1] = t1.y; w21[2] = t1.z; w21[3] = t1.w;
    }

    float v10 = 0.f, v11 = 0.f, v12 = 0.f, v13 = 0.f;
    float v2a = 0.f, v2b = 0.f;

    // 8-deep prefetch ring for y rows (512 B/warp/step, DRAM latency hiding)
    float4 ybuf[8];
#pragma unroll
    for (int i = 0; i < 8; i++) ybuf[i] = *(const float4*)(yb + (size_t)i * D_);

    // reduction pipeline stages (stage s holds step t-s, reduced s levels)
    float a0 = 0.f, a1 = 0.f;   // partials, 0 levels
    float b0 = 0.f, b1 = 0.f;   // 1 level  (xor 16)
    float c0 = 0.f, c1 = 0.f;   // 2 levels (xor 8)
    float d0 = 0.f, d1 = 0.f;   // 3 levels (xor 4)
    float e0 = 0.f, e1 = 0.f;   // 4 levels (xor 2)

    for (int t = 0; t < T_ + 5; t++) {
        // final level + v2 update for step (t-5)
        if (t >= 5) {
            float r0 = e0 + __shfl_xor_sync(FULL, e0, 1);
            float r1 = e1 + __shfl_xor_sync(FULL, e1, 1);
            v2a += r0; v2b += r1;
            float s2a = (v2a >= 1.f) ? 1.f : 0.f;
            float s2b = (v2b >= 1.f) ? 1.f : 0.f;
            if (lane == 0) {
                float2 ov = make_float2(s2a, s2b);
                *(float2*)(ob + (size_t)(t - 5) * O_) = ov;
            }
            v2a = (v2a >= 1.f) ? 0.f : v2a;
            v2b = (v2b >= 1.f) ? 0.f : v2b;
        }

        // advance pipeline (read old stage before overwriting it: e<=d<=c<=b<=a)
        e0 = d0 + __shfl_xor_sync(FULL, d0, 2);  e1 = d1 + __shfl_xor_sync(FULL, d1, 2);
        d0 = c0 + __shfl_xor_sync(FULL, c0, 4);  d1 = c1 + __shfl_xor_sync(FULL, c1, 4);
        c0 = b0 + __shfl_xor_sync(FULL, b0, 8);  c1 = b1 + __shfl_xor_sync(FULL, b1, 8);
        b0 = a0 + __shfl_xor_sync(FULL, a0, 16); b1 = a1 + __shfl_xor_sync(FULL, a1, 16);

        // layer-1 update for step t, produce new partials
        if (t < T_) {
            float4 y = ybuf[t & 7];
            if (t + 8 < T_) ybuf[t & 7] = *(const float4*)(yb + (size_t)(t + 8) * D_);

            v10 += y.x; v11 += y.y; v12 += y.z; v13 += y.w;

            float s0 = (v10 >= 1.f) ? 1.f : 0.f;
            float s1 = (v11 >= 1.f) ? 1.f : 0.f;
            float s2 = (v12 >= 1.f) ? 1.f : 0.f;
            float s3 = (v13 >= 1.f) ? 1.f : 0.f;

            float p0, p1;
            p0 = s0 * w20[0];            p1 = s0 * w21[0];
            p0 = fmaf(s1, w20[1], p0);   p1 = fmaf(s1, w21[1], p1);
            p0 = fmaf(s2, w20[2], p0);   p1 = fmaf(s2, w21[2], p1);
            p0 = fmaf(s3, w20[3], p0);   p1 = fmaf(s3, w21[3], p1);

            v10 = (s0 > 0.f) ? 0.f : v10;
            v11 = (s1 > 0.f) ? 0.f : v11;
            v12 = (s2 > 0.f) ? 0.f : v12;
            v13 = (s3 > 0.f) ? 0.f : v13;

            a0 = p0; a1 = p1;
        } else {
            a0 = 0.f; a1 = 0.f;
        }
    }
}

// ---------------------------------------------------------------------------
extern "C" void kernel_launch(void* const* d_in, const int* in_sizes, int n_in,
                              void* d_out, int out_size)
{
    const float* x  = (const float*)d_in[0];   // [128, 4096, 128] f32
    const float* W1 = (const float*)d_in[1];   // [128, 128]  (row = d, col = k)
    const float* W2 = (const float*)d_in[2];   // [2, 128]
    float* out = (float*)d_out;                // [128, 4096, 2] f32

    gemm_xw1<<<(B_ * T_) / 128, 256>>>(x, W1);
    snn_scan<<<B_, 32>>>(W2, out);
}

// round 2
// speedup vs baseline: 3.8849x; 3.8849x over previous
#include <cuda_runtime.h>
#include <cstdint>

// ---------------------------------------------------------------------------
// BeatDetectionRSNN2: 2-layer IF-neuron SNN.
//   K1: Y[b,t,d] = sum_k x[b,t,k] * W1[d,k]          (big fp32 GEMM, parallel)
//   K2: serial scan over t per batch b:
//         v1 += y_t; s1 = (v1>=1); v1 *= (1-s1)
//         v2 += s1 @ W2^T; s2 = (v2>=1); v2 *= (1-s2); out = s2
// ---------------------------------------------------------------------------

#define B_  128
#define T_  4096
#define D_  128
#define O_  2

// 256 MB scratch for Y (device global => no allocation in kernel_launch)
__device__ float g_Y[(size_t)B_ * T_ * D_];

// packed fp32x2 FMA (sm_100a) — ptxas will not auto-generate FFMA2
union F2U { float2 f; unsigned long long u; };
__device__ __forceinline__ float2 fma2(float2 a, float2 b, float2 c) {
    F2U A, Bv, C, Dv; A.f = a; Bv.f = b; C.f = c;
    asm("fma.rn.f32x2 %0, %1, %2, %3;" : "=l"(Dv.u) : "l"(A.u), "l"(Bv.u), "l"(C.u));
    return Dv.f;
}

// ---------------------------------------------------------------------------
// K1: tiled fp32 GEMM, C[M=524288,128] = X[M,128] * W1^T
// Block tile 128x128, K-chunk 32, 256 threads, 8x8 micro-tile via FFMA2.
// ---------------------------------------------------------------------------
#define BK 32
#define LDP 132   // padded row pitch (floats) for k-major smem tiles

__global__ __launch_bounds__(256, 2)
void gemm_xw1(const float* __restrict__ X, const float* __restrict__ W1)
{
    __shared__ float As[BK * LDP];   // As[k][m], m contiguous
    __shared__ float Bs[BK * LDP];   // Bs[k][n], n contiguous (= W1[n][k])

    const int tid = threadIdx.x;
    const int tx  = tid & 15;        // n-tile index  (n0 = tx*8)
    const int ty  = tid >> 4;        // m-tile index  (m0 = ty*8)
    const int m0  = blockIdx.x * 128;

    const int rl = tid >> 3;         // 0..31 row within load pass
    const int c4 = (tid & 7) * 4;    // 0,4,...,28 col within K-chunk

    float2 acc[8][4];
#pragma unroll
    for (int i = 0; i < 8; i++)
#pragma unroll
        for (int j = 0; j < 4; j++) acc[i][j] = make_float2(0.f, 0.f);

    for (int kc = 0; kc < 128; kc += BK) {
#pragma unroll
        for (int rr = 0; rr < 128; rr += 32) {
            float4 v = *(const float4*)&X[(size_t)(m0 + rr + rl) * 128 + kc + c4];
            As[(c4 + 0) * LDP + rr + rl] = v.x;
            As[(c4 + 1) * LDP + rr + rl] = v.y;
            As[(c4 + 2) * LDP + rr + rl] = v.z;
            As[(c4 + 3) * LDP + rr + rl] = v.w;
        }
#pragma unroll
        for (int nn = 0; nn < 128; nn += 32) {
            float4 v = *(const float4*)&W1[(size_t)(nn + rl) * 128 + kc + c4];
            Bs[(c4 + 0) * LDP + nn + rl] = v.x;
            Bs[(c4 + 1) * LDP + nn + rl] = v.y;
            Bs[(c4 + 2) * LDP + nn + rl] = v.z;
            Bs[(c4 + 3) * LDP + nn + rl] = v.w;
        }
        __syncthreads();

#pragma unroll
        for (int k = 0; k < BK; k++) {
            const float* ap = &As[k * LDP + ty * 8];
            const float* bp = &Bs[k * LDP + tx * 8];
            float4 a0 = *(const float4*)(ap);
            float4 a1 = *(const float4*)(ap + 4);
            float4 b0 = *(const float4*)(bp);
            float4 b1 = *(const float4*)(bp + 4);
            float  av[8] = {a0.x, a0.y, a0.z, a0.w, a1.x, a1.y, a1.z, a1.w};
            float2 bv[4] = {{b0.x, b0.y}, {b0.z, b0.w}, {b1.x, b1.y}, {b1.z, b1.w}};
#pragma unroll
            for (int i = 0; i < 8; i++) {
                float2 ad = make_float2(av[i], av[i]);
#pragma unroll
                for (int j = 0; j < 4; j++)
                    acc[i][j] = fma2(ad, bv[j], acc[i][j]);
            }
        }
        __syncthreads();
    }

    const int row0 = m0 + ty * 8;
    const int col0 = tx * 8;
#pragma unroll
    for (int i = 0; i < 8; i++) {
        float4 o0 = make_float4(acc[i][0].x, acc[i][0].y, acc[i][1].x, acc[i][1].y);
        float4 o1 = make_float4(acc[i][2].x, acc[i][2].y, acc[i][3].x, acc[i][3].y);
        *(float4*)&g_Y[(size_t)(row0 + i) * 128 + col0]     = o0;
        *(float4*)&g_Y[(size_t)(row0 + i) * 128 + col0 + 4] = o1;
    }
}

// ---------------------------------------------------------------------------
// K2: serial scan. One warp per batch element. Lane l owns d = 4l..4l+3.
//  - 16-deep register prefetch ring, STATIC indices (fully unrolled 16-step
//    blocks) so the ring never touches local memory.
//  - 5-level butterfly reduction software-pipelined one level per step
//    (output delayed 5 steps) -> no shfl chain on the critical path.
//  - steady-state block has no runtime branches (store is @lane0-predicated).
// ---------------------------------------------------------------------------

// One scan step. t: step index (may be compile-time or runtime),
// J: literal ring slot, PRE: prefetch row t+16, GRD: guard store with t>=5,
// LD: consume a y row (false during drain).
#define STEP(t, J, PRE, GRD, LD)                                              \
{                                                                             \
    /* finalize step (t)-5: last butterfly level + v2 update */               \
    float r0 = e0 + __shfl_xor_sync(FULL, e0, 1);                             \
    float r1 = e1 + __shfl_xor_sync(FULL, e1, 1);                             \
    v2a += r0; v2b += r1;                                                     \
    bool f2a = (v2a >= 1.f), f2b = (v2b >= 1.f);                              \
    if ((!(GRD) || (t) >= 5) && lane == 0) {                                  \
        float2 ov = make_float2(f2a ? 1.f : 0.f, f2b ? 1.f : 0.f);            \
        *(float2*)(ob + (size_t)((t) - 5) * O_) = ov;                         \
    }                                                                         \
    if (f2a) v2a = 0.f;                                                       \
    if (f2b) v2b = 0.f;                                                       \
    /* advance pipeline (read old stage before overwriting) */                \
    e0 = d0 + __shfl_xor_sync(FULL, d0, 2);                                   \
    e1 = d1 + __shfl_xor_sync(FULL, d1, 2);                                   \
    d0 = c0 + __shfl_xor_sync(FULL, c0, 4);                                   \
    d1 = c1 + __shfl_xor_sync(FULL, c1, 4);                                   \
    c0 = b0 + __shfl_xor_sync(FULL, b0, 8);                                   \
    c1 = b1 + __shfl_xor_sync(FULL, b1, 8);                                   \
    b0 = a0 + __shfl_xor_sync(FULL, a0, 16);                                  \
    b1 = a1 + __shfl_xor_sync(FULL, a1, 16);                                  \
    if (LD) {                                                                 \
        float4 y = ybuf[J];                                                   \
        if (PRE) ybuf[J] = *(const float4*)(yb + (size_t)((t) + 16) * D_);    \
        v10 += y.x; v11 += y.y; v12 += y.z; v13 += y.w;                       \
        bool s0 = (v10 >= 1.f), s1 = (v11 >= 1.f);                            \
        bool s2 = (v12 >= 1.f), s3 = (v13 >= 1.f);                            \
        float p0a = (s0 ? w20[0] : 0.f) + (s1 ? w20[1] : 0.f);                \
        float p0b = (s2 ? w20[2] : 0.f) + (s3 ? w20[3] : 0.f);                \
        float p1a = (s0 ? w21[0] : 0.f) + (s1 ? w21[1] : 0.f);                \
        float p1b = (s2 ? w21[2] : 0.f) + (s3 ? w21[3] : 0.f);                \
        a0 = p0a + p0b;                                                       \
        a1 = p1a + p1b;                                                       \
        if (s0) v10 = 0.f;                                                    \
        if (s1) v11 = 0.f;                                                    \
        if (s2) v12 = 0.f;                                                    \
        if (s3) v13 = 0.f;                                                    \
    } else {                                                                  \
        a0 = 0.f; a1 = 0.f;                                                   \
    }                                                                         \
}

__global__ void snn_scan(const float* __restrict__ W2, float* __restrict__ out)
{
    const int b    = blockIdx.x;
    const int lane = threadIdx.x;           // 0..31
    const unsigned FULL = 0xffffffffu;

    const float* yb = g_Y + (size_t)b * T_ * D_ + lane * 4;
    float* ob = out + (size_t)b * T_ * O_;

    float w20[4], w21[4];
    {
        float4 t0 = *(const float4*)(W2 + lane * 4);
        float4 t1 = *(const float4*)(W2 + 128 + lane * 4);
        w20[0] = t0.x; w20[1] = t0.y; w20[2] = t0.z; w20[3] = t0.w;
        w21[0] = t1.x; w21[1] = t1.y; w21[2] = t1.z; w21[3] = t1.w;
    }

    float v10 = 0.f, v11 = 0.f, v12 = 0.f, v13 = 0.f;
    float v2a = 0.f, v2b = 0.f;

    // 16-deep register prefetch ring (static indices only!)
    float4 ybuf[16];
#pragma unroll
    for (int i = 0; i < 16; i++) ybuf[i] = *(const float4*)(yb + (size_t)i * D_);

    // reduction pipeline stages (stage s holds step t-1-s', see STEP)
    float a0 = 0.f, a1 = 0.f;
    float b0 = 0.f, b1 = 0.f;
    float c0 = 0.f, c1 = 0.f;
    float d0 = 0.f, d1 = 0.f;
    float e0 = 0.f, e1 = 0.f;

    // ---- prologue: t = 0..15 (store guard folds: t literal) ----
#pragma unroll
    for (int j = 0; j < 16; j++) {
        STEP(j, j, 1, 1, 1);
    }

    // ---- steady: t0 = 16 .. T_-32, no guards, prefetch valid ----
    for (int t0 = 16; t0 < T_ - 16; t0 += 16) {
#pragma unroll
        for (int j = 0; j < 16; j++) {
            STEP(t0 + j, j, 1, 0, 1);
        }
    }

    // ---- tail: t0 = T_-16, no prefetch ----
    {
        const int t0 = T_ - 16;
#pragma unroll
        for (int j = 0; j < 16; j++) {
            STEP(t0 + j, j, 0, 0, 1);
        }
    }

    // ---- drain: 5 steps, no y, flush pipeline (outputs T_-5 .. T_-1) ----
#pragma unroll
    for (int k = 0; k < 5; k++) {
        STEP(T_ + k, 0, 0, 0, 0);
    }
}

// ---------------------------------------------------------------------------
extern "C" void kernel_launch(void* const* d_in, const int* in_sizes, int n_in,
                              void* d_out, int out_size)
{
    const float* x  = (const float*)d_in[0];   // [128, 4096, 128] f32
    const float* W1 = (const float*)d_in[1];   // [128, 128]
    const float* W2 = (const float*)d_in[2];   // [2, 128]
    float* out = (float*)d_out;                // [128, 4096, 2] f32

    gemm_xw1<<<(B_ * T_) / 128, 256>>>(x, W1);
    snn_scan<<<B_, 32>>>(W2, out);
}